// round 14
// baseline (speedup 1.0000x reference)
#include <cuda_runtime.h>
#include <cuda_fp16.h>
#include <math.h>
#include <stdint.h>

#define BATCH   128
#define NWIN    16
#define NTOK    512
#define DIM     256
#define NH      8
#define HD      32
#define TABLE_E 3375
#define QKV_LD  768
#define NN      (NTOK*NTOK)
#define LOG2E   1.4426950408889634f
#define NFRAG   65536
#define ONES_H2 0x3C003C00u
#define SCALE2  (0.17677669529663687f * LOG2E)
#define RAWK    (65536.f / 24.f)         // raw units per log2-unit
#define KDEC    (24.f / 65536.f)         // log2-units per raw unit

// ---------------- scratch (device globals) ----------------
__device__ float  g_table[TABLE_E * NH];
__device__ uint4  g_biasU[NH * 32768];      // u16 fixed-point bias (raw units), 4 MB
__device__ float4 g_maskF[NWIN * NFRAG];    // fragment-layout mask (raw units)
__device__ int    g_maskflag;
__device__ __half g_xh[(size_t)BATCH * NTOK * DIM];
__device__ __half g_qkvw[QKV_LD * DIM];
__device__ __half g_projw[DIM * DIM];
__device__ __half g_qkv[(size_t)BATCH * NTOK * QKV_LD];   // Q pre-scaled to raw units
__device__ __half g_att[(size_t)BATCH * NTOK * DIM];

// =====================  helpers  =====================
__device__ __forceinline__ uint32_t pack_half2(float lo, float hi) {
    __half2 h = __floats2half2_rn(lo, hi);
    return *(uint32_t*)&h;
}
__device__ __forceinline__ uint32_t ex2_h2(float lo, float hi) {
    uint32_t d = pack_half2(lo, hi), r;
    asm("ex2.approx.f16x2 %0, %1;" : "=r"(r) : "r"(d));
    return r;
}
__device__ __forceinline__ void mma_f16(float* d, const uint32_t* a,
                                        uint32_t b0, uint32_t b1) {
    asm volatile(
        "mma.sync.aligned.m16n8k16.row.col.f32.f16.f16.f32 "
        "{%0,%1,%2,%3}, {%4,%5,%6,%7}, {%8,%9}, {%0,%1,%2,%3};"
        : "+f"(d[0]), "+f"(d[1]), "+f"(d[2]), "+f"(d[3])
        : "r"(a[0]), "r"(a[1]), "r"(a[2]), "r"(a[3]), "r"(b0), "r"(b1));
}
__device__ __forceinline__ void ldsm4(uint32_t* r, uint32_t addr) {
    asm volatile("ldmatrix.sync.aligned.m8n8.x4.shared.b16 {%0,%1,%2,%3}, [%4];"
                 : "=r"(r[0]), "=r"(r[1]), "=r"(r[2]), "=r"(r[3]) : "r"(addr));
}
__device__ __forceinline__ void ldsm4t(uint32_t* r, uint32_t addr) {
    asm volatile("ldmatrix.sync.aligned.m8n8.x4.trans.shared.b16 {%0,%1,%2,%3}, [%4];"
                 : "=r"(r[0]), "=r"(r[1]), "=r"(r[2]), "=r"(r[3]) : "r"(addr));
}
__device__ __forceinline__ uint32_t cvta_s(const void* p) {
    return (uint32_t)__cvta_generic_to_shared(p);
}
__device__ __forceinline__ uint32_t swz(int r, int kchunk) {
    return (uint32_t)(r * 64 + ((kchunk ^ ((r >> 1) & 3)) << 4));
}
__device__ __forceinline__ uint32_t swz128(int r, int kchunk) {
    return (uint32_t)(r * 128 + ((kchunk ^ (r & 7)) << 4));
}
__device__ __forceinline__ void cp16(uint32_t smem, const void* g) {
    asm volatile("cp.async.cg.shared.global [%0], [%1], 16;"
                 :: "r"(smem), "l"(g) : "memory");
}
__device__ __forceinline__ void cp_commit() {
    asm volatile("cp.async.commit_group;" ::: "memory");
}
__device__ __forceinline__ void cp_wait0() {
    asm volatile("cp.async.wait_group 0;" ::: "memory");
}
__device__ __forceinline__ void cp_wait1() {
    asm volatile("cp.async.wait_group 1;" ::: "memory");
}

// ---------------- prep0: fp32->fp16 conversions + CPB MLP ----------------
#define N8X ((BATCH * NTOK * DIM) / 8)
#define N8W ((QKV_LD * DIM) / 8)
#define N8P ((DIM * DIM) / 8)
#define N8T (N8X + N8W + N8P)
#define NCVT_BLK ((N8T + 255) / 256)
__global__ void prep0(const float* __restrict__ x,
                      const float* __restrict__ qw,
                      const float* __restrict__ pw,
                      const float* __restrict__ rpb,
                      const float* __restrict__ w1,
                      const float* __restrict__ b1,
                      const float* __restrict__ w2) {
    int bx = blockIdx.x;
    if (bx < NCVT_BLK) {
        int i = bx * 256 + threadIdx.x;
        if (i == 0) g_maskflag = 0;
        const float* s;
        __half* d;
        int j;
        if (i < N8X)                  { s = x;  d = g_xh;    j = i; }
        else if (i < N8X + N8W)       { s = qw; d = g_qkvw;  j = i - N8X; }
        else if (i < N8T)             { s = pw; d = g_projw; j = i - N8X - N8W; }
        else return;
        const float4* sp = (const float4*)s + (size_t)j * 2;
        float4 a = sp[0], b = sp[1];
        uint4 o;
        o.x = pack_half2(a.x, a.y); o.y = pack_half2(a.z, a.w);
        o.z = pack_half2(b.x, b.y); o.w = pack_half2(b.z, b.w);
        ((uint4*)d)[j] = o;
    } else {
        int e = bx - NCVT_BLK;
        int h = threadIdx.x >> 5;
        int lane = threadIdx.x & 31;
        float r0 = rpb[e * 3 + 0], r1 = rpb[e * 3 + 1], r2 = rpb[e * 3 + 2];
        float sum = 0.f;
        for (int o = lane; o < 512; o += 32) {
            float hid = fmaf(r0, w1[o * 3 + 0],
                        fmaf(r1, w1[o * 3 + 1],
                        fmaf(r2, w1[o * 3 + 2], b1[o])));
            hid = fmaxf(hid, 0.f);
            sum = fmaf(hid, w2[h * 512 + o], sum);
        }
        #pragma unroll
        for (int off = 16; off; off >>= 1)
            sum += __shfl_xor_sync(0xffffffffu, sum, off);
        if (lane == 0) g_table[e * NH + h] = sum;
    }
}

// ---------------- prep1: maskF (raw units) + biasU (u16) -------------------
__global__ void prep1(const float* __restrict__ mask,
                      const int* __restrict__ rpb_idx) {
    int bx = blockIdx.x;
    if (bx < 4096) {
        int w = bx >> 8;
        int i = (bx & 255) * 256 + threadIdx.x;
        int g = i & 7, t = (i >> 3) & 3, jn = (i >> 5) & 7, c = (i >> 8) & 7;
        int wid = (i >> 11) & 7, qt = i >> 14;
        int q0 = qt * 128 + wid * 16 + g;
        int k0 = c * 64 + jn * 8 + 2 * t;
        const float* mw = mask + (size_t)w * NN;
        float4 v;
        v.x = mw[q0 * NTOK + k0];
        v.y = mw[q0 * NTOK + k0 + 1];
        v.z = mw[(q0 + 8) * NTOK + k0];
        v.w = mw[(q0 + 8) * NTOK + k0 + 1];
        bool nz = (v.x != 0.f) | (v.y != 0.f) | (v.z != 0.f) | (v.w != 0.f);
        const float MS = LOG2E * RAWK;
        v.x *= MS; v.y *= MS; v.z *= MS; v.w *= MS;
        g_maskF[(size_t)w * NFRAG + i] = v;
        if (__syncthreads_or(nz) && threadIdx.x == 0)
            atomicOr(&g_maskflag, 1);
    } else {
        int i = (bx - 4096) * 256 + threadIdx.x;
        int g = i & 7, t = (i >> 3) & 3, jp = (i >> 5) & 1, sh = (i >> 6) & 1;
        int c = (i >> 7) & 7, we = (i >> 10) & 7, qt = i >> 13;
        int q0 = qt * 128 + we * 16 + g;
        int kbase = c * 64 + sh * 32 + jp * 16 + 2 * t;
        int idx[8];
        #pragma unroll
        for (int jj = 0; jj < 2; jj++) {
            int k0 = kbase + jj * 8;
            idx[jj * 4 + 0] = rpb_idx[q0 * NTOK + k0];
            idx[jj * 4 + 1] = rpb_idx[q0 * NTOK + k0 + 1];
            idx[jj * 4 + 2] = rpb_idx[(q0 + 8) * NTOK + k0];
            idx[jj * 4 + 3] = rpb_idx[(q0 + 8) * NTOK + k0 + 1];
        }
        const float KENC = 16.f * LOG2E * RAWK;
        size_t obase = (size_t)qt * 8192 + we * 1024 + c * 128 + sh * 64
                     + jp * 32 + t * 8 + g;
        #pragma unroll
        for (int h = 0; h < NH; h++) {
            uint32_t u[8];
            #pragma unroll
            for (int v = 0; v < 8; v++) {
                float val = KENC / (1.f + __expf(-g_table[idx[v] * NH + h]));
                u[v] = (uint32_t)(val + 0.5f);
            }
            uint4 o4;
            o4.x = u[0] | (u[1] << 16);
            o4.y = u[2] | (u[3] << 16);
            o4.z = u[4] | (u[5] << 16);
            o4.w = u[6] | (u[7] << 16);
            g_biasU[(size_t)h * 32768 + obase] = o4;
        }
    }
}

// =====================  fp16 mma GEMM (NT), 64x64 warp tiles, BK=64  =====
#define GSMEM (4 * 16384)
__global__ __launch_bounds__(128, 2) void gemm_h(const __half* __restrict__ A,
                                                 const __half* __restrict__ B,
                                                 const float* __restrict__ bias,
                                                 void* __restrict__ Cv,
                                                 int M, int N, int K, int fp32out,
                                                 int qcols, float qsc) {
    extern __shared__ __align__(16) char gsm[];
    const int tid = threadIdx.x, lane = tid & 31, wid = tid >> 5;
    const int g = lane >> 2, t = lane & 3;
    const int wm = wid & 1, wn = wid >> 1;
    const int row0 = blockIdx.y * 128, col0 = blockIdx.x * 128;

    const int lr0 = tid >> 3, lc = tid & 7;
    const __half* Ap = A + (size_t)(row0 + lr0) * K + lc * 8;
    const __half* Bp = B + (size_t)(col0 + lr0) * K + lc * 8;
    const size_t rstep = (size_t)16 * K;
    uint32_t aS[2] = { cvta_s(gsm), cvta_s(gsm) + 16384 };
    uint32_t bS[2] = { cvta_s(gsm) + 32768, cvta_s(gsm) + 49152 };
    uint32_t soffs[8];
    #pragma unroll
    for (int i = 0; i < 8; i++) soffs[i] = swz128(lr0 + i * 16, lc);

    float acc[4][8][4];
    #pragma unroll
    for (int mt = 0; mt < 4; mt++)
        #pragma unroll
        for (int jn = 0; jn < 8; jn++)
            #pragma unroll
            for (int r = 0; r < 4; r++) acc[mt][jn][r] = 0.f;

    #pragma unroll
    for (int i = 0; i < 8; i++) {
        cp16(aS[0] + soffs[i], Ap + i * rstep);
        cp16(bS[0] + soffs[i], Bp + i * rstep);
    }
    cp_commit();

    const int nk = K >> 6;
    for (int kt = 0; kt < nk; kt++) {
        const int s = kt & 1;
        cp_wait0();
        __syncthreads();
        if (kt + 1 < nk) {
            int ko = (kt + 1) * 64;
            #pragma unroll
            for (int i = 0; i < 8; i++) {
                cp16(aS[s ^ 1] + soffs[i], Ap + i * rstep + ko);
                cp16(bS[s ^ 1] + soffs[i], Bp + i * rstep + ko);
            }
            cp_commit();
        }
        #pragma unroll
        for (int ks = 0; ks < 4; ks++) {
            uint32_t af[4][4];
            #pragma unroll
            for (int mt = 0; mt < 4; mt++) {
                int row = wm * 64 + mt * 16 + (lane & 15);
                int kch = ks * 2 + (lane >> 4);
                ldsm4(af[mt], aS[s] + swz128(row, kch));
            }
            uint32_t bf[4][4];
            #pragma unroll
            for (int i = 0; i < 4; i++) {
                int rn = wn * 64 + i * 16 + ((lane >> 4) << 3) + (lane & 7);
                int kch = ks * 2 + ((lane & 8) >> 3);
                ldsm4(bf[i], bS[s] + swz128(rn, kch));
            }
            #pragma unroll
            for (int mt = 0; mt < 4; mt++)
                #pragma unroll
                for (int jn = 0; jn < 8; jn++)
                    mma_f16(acc[mt][jn], af[mt],
                            bf[jn >> 1][(jn & 1) * 2], bf[jn >> 1][(jn & 1) * 2 + 1]);
        }
        // no trailing sync: next iteration's wait+sync orders buffer reuse
    }

    if (fp32out) {
        float* C = (float*)Cv;
        #pragma unroll
        for (int mt = 0; mt < 4; mt++) {
            int r = row0 + wm * 64 + mt * 16;
            #pragma unroll
            for (int jn = 0; jn < 8; jn++) {
                int cc = col0 + wn * 64 + jn * 8 + 2 * t;
                float bx = bias[cc], by = bias[cc + 1];
                float2 v0 = { acc[mt][jn][0] + bx, acc[mt][jn][1] + by };
                float2 v1 = { acc[mt][jn][2] + bx, acc[mt][jn][3] + by };
                *(float2*)(C + (size_t)(r + g) * N + cc) = v0;
                *(float2*)(C + (size_t)(r + g + 8) * N + cc) = v1;
            }
        }
    } else {
        __half* C = (__half*)Cv;
        #pragma unroll
        for (int mt = 0; mt < 4; mt++) {
            int r = row0 + wm * 64 + mt * 16;
            #pragma unroll
            for (int jn = 0; jn < 8; jn++) {
                int cc = col0 + wn * 64 + jn * 8 + 2 * t;
                float sc_ = (cc < qcols) ? qsc : 1.f;
                *(uint32_t*)(C + (size_t)(r + g) * N + cc)
                    = pack_half2(acc[mt][jn][0] * sc_, acc[mt][jn][1] * sc_);
                *(uint32_t*)(C + (size_t)(r + g + 8) * N + cc)
                    = pack_half2(acc[mt][jn][2] * sc_, acc[mt][jn][3] * sc_);
            }
        }
    }
}

// =====================  fused fp16 mma attention ============================
// 3-deep cp.async pipeline; single sync/chunk; rescale-skip; raw-unit softmax
__global__ __launch_bounds__(128, 3) void attn_h() {
    __shared__ __align__(16) __half Ks[3][64 * 32];
    __shared__ __align__(16) __half Vs[3][64 * 32];
    const int qt = blockIdx.x, h = blockIdx.y, b = blockIdx.z;
    const int tid = threadIdx.x, lane = tid & 31, w = tid >> 5;
    const int g = lane >> 2, t = lane & 3;
    const int q0 = qt * 128 + w * 32;
    const __half* base = g_qkv + (size_t)b * NTOK * QKV_LD;
    const bool use_mask = (g_maskflag != 0);

    const __half* kp0 = base + (size_t)(tid >> 2) * QKV_LD + DIM + h * HD + (tid & 3) * 8;
    const __half* kp1 = base + (size_t)((tid + 128) >> 2) * QKV_LD + DIM + h * HD
                             + ((tid + 128) & 3) * 8;
    const uint32_t sf0 = swz(tid >> 2, tid & 3);
    const uint32_t sf1 = swz((tid + 128) >> 2, (tid + 128) & 3);
    const uint32_t kS[3] = { cvta_s(Ks[0]), cvta_s(Ks[1]), cvta_s(Ks[2]) };
    const uint32_t vS[3] = { cvta_s(Vs[0]), cvta_s(Vs[1]), cvta_s(Vs[2]) };

    // prologue: stage chunks 0 and 1 (two groups)
    cp16(kS[0] + sf0, kp0);
    cp16(kS[0] + sf1, kp1);
    cp16(vS[0] + sf0, kp0 + DIM);
    cp16(vS[0] + sf1, kp1 + DIM);
    cp_commit();
    {
        const size_t nb = (size_t)64 * QKV_LD;
        cp16(kS[1] + sf0, kp0 + nb);
        cp16(kS[1] + sf1, kp1 + nb);
        cp16(vS[1] + sf0, kp0 + nb + DIM);
        cp16(vS[1] + sf1, kp1 + nb + DIM);
        cp_commit();
    }

    uint32_t qa[2][2][4];   // Q already in raw units
    #pragma unroll
    for (int mt = 0; mt < 2; mt++) {
        const __half* qp0 = base + (size_t)(q0 + mt * 16 + g) * QKV_LD + h * HD;
        const __half* qp8 = qp0 + (size_t)8 * QKV_LD;
        #pragma unroll
        for (int ks = 0; ks < 2; ks++) {
            qa[mt][ks][0] = *(const uint32_t*)(qp0 + ks * 16 + 2 * t);
            qa[mt][ks][1] = *(const uint32_t*)(qp8 + ks * 16 + 2 * t);
            qa[mt][ks][2] = *(const uint32_t*)(qp0 + ks * 16 + 8 + 2 * t);
            qa[mt][ks][3] = *(const uint32_t*)(qp8 + ks * 16 + 8 + 2 * t);
        }
    }

    float o[2][4][4];
    float lacc[2][4];
    #pragma unroll
    for (int mt = 0; mt < 2; mt++) {
        #pragma unroll
        for (int nd = 0; nd < 4; nd++)
            #pragma unroll
            for (int r = 0; r < 4; r++) o[mt][nd][r] = 0.f;
        #pragma unroll
        for (int r = 0; r < 4; r++) lacc[mt][r] = 0.f;
    }
    float m[2][2] = { { -1e30f, -1e30f }, { -1e30f, -1e30f } };

    const uint4* bU[2];
    const float4* mp4[2];
    #pragma unroll
    for (int mt = 0; mt < 2; mt++) {
        int we = w * 2 + mt;
        bU[mt] = g_biasU + (size_t)h * 32768 + (size_t)qt * 8192 + we * 1024
               + t * 8 + g;
        mp4[mt] = g_maskF + (((size_t)(b & (NWIN - 1)) * 4 + qt) * 8 + we) * 2048
                + t * 8 + g;
    }

    int s = 0;
    for (int c = 0; c < 8; c++) {
        cp_wait1();          // chunk c arrived (chunk c+1 may still be in flight)
        __syncthreads();     // all warps done with buffer we are about to refill
        if (c + 2 < 8) {
            int s2 = (s >= 1) ? s - 1 : 2;   // (s+2) % 3
            const size_t nb = (size_t)(c + 2) * 64 * QKV_LD;
            cp16(kS[s2] + sf0, kp0 + nb);
            cp16(kS[s2] + sf1, kp1 + nb);
            cp16(vS[s2] + sf0, kp0 + nb + DIM);
            cp16(vS[s2] + sf1, kp1 + nb + DIM);
        }
        cp_commit();         // always commit (empty group keeps wait1 aligned)

        // two 32-key sub-chunks
        #pragma unroll
        for (int sh = 0; sh < 2; sh++) {
            // ---- S init = bias (u16 decode, raw units) (+ mask) ----
            float sc[2][4][4];
            #pragma unroll
            for (int mt = 0; mt < 2; mt++) {
                const uint4* bu = bU[mt] + c * 128 + sh * 64;
                uint4 U0 = bu[0];
                uint4 U1 = bu[32];
                sc[mt][0][0] = (float)(U0.x & 0xffffu); sc[mt][0][1] = (float)(U0.x >> 16);
                sc[mt][0][2] = (float)(U0.y & 0xffffu); sc[mt][0][3] = (float)(U0.y >> 16);
                sc[mt][1][0] = (float)(U0.z & 0xffffu); sc[mt][1][1] = (float)(U0.z >> 16);
                sc[mt][1][2] = (float)(U0.w & 0xffffu); sc[mt][1][3] = (float)(U0.w >> 16);
                sc[mt][2][0] = (float)(U1.x & 0xffffu); sc[mt][2][1] = (float)(U1.x >> 16);
                sc[mt][2][2] = (float)(U1.y & 0xffffu); sc[mt][2][3] = (float)(U1.y >> 16);
                sc[mt][3][0] = (float)(U1.z & 0xffffu); sc[mt][3][1] = (float)(U1.z >> 16);
                sc[mt][3][2] = (float)(U1.w & 0xffffu); sc[mt][3][3] = (float)(U1.w >> 16);
                if (use_mask) {
                    const float4* mc = mp4[mt] + c * 256 + sh * 128;
                    #pragma unroll
                    for (int jn = 0; jn < 4; jn++) {
                        float4 mv = mc[jn * 32];
                        sc[mt][jn][0] += mv.x; sc[mt][jn][1] += mv.y;
                        sc[mt][jn][2] += mv.z; sc[mt][jn][3] += mv.w;
                    }
                }
            }
            // ---- S += Q K^T (raw units) ----
            #pragma unroll
            for (int ks = 0; ks < 2; ks++) {
                uint32_t kb[2][4];
                #pragma unroll
                for (int i = 0; i < 2; i++) {
                    int rn = sh * 32 + i * 16 + ((lane >> 4) << 3) + (lane & 7);
                    int kch = ks * 2 + ((lane & 8) >> 3);
                    ldsm4(kb[i], kS[s] + swz(rn, kch));
                }
                #pragma unroll
                for (int jn = 0; jn < 4; jn++) {
                    uint32_t b0 = kb[jn >> 1][(jn & 1) * 2];
                    uint32_t b1 = kb[jn >> 1][(jn & 1) * 2 + 1];
                    mma_f16(sc[0][jn], qa[0][ks], b0, b1);
                    mma_f16(sc[1][jn], qa[1][ks], b0, b1);
                }
            }

            // ---- online softmax (raw units, rescale-skip) ----
            uint32_t pa[2][2][4];
            #pragma unroll
            for (int mt = 0; mt < 2; mt++) {
                float mx0 = sc[mt][0][0], mx1 = sc[mt][0][2];
                #pragma unroll
                for (int jn = 0; jn < 4; jn++) {
                    mx0 = fmaxf(mx0, fmaxf(sc[mt][jn][0], sc[mt][jn][1]));
                    mx1 = fmaxf(mx1, fmaxf(sc[mt][jn][2], sc[mt][jn][3]));
                }
                mx0 = fmaxf(mx0, __shfl_xor_sync(0xffffffffu, mx0, 1));
                mx0 = fmaxf(mx0, __shfl_xor_sync(0xffffffffu, mx0, 2));
                mx1 = fmaxf(mx1, __shfl_xor_sync(0xffffffffu, mx1, 1));
                mx1 = fmaxf(mx1, __shfl_xor_sync(0xffffffffu, mx1, 2));
                if (mx0 > m[mt][0] || mx1 > m[mt][1]) {
                    float nm0 = fmaxf(m[mt][0], mx0), nm1 = fmaxf(m[mt][1], mx1);
                    float c0 = exp2f((m[mt][0] - nm0) * KDEC);
                    float c1 = exp2f((m[mt][1] - nm1) * KDEC);
                    m[mt][0] = nm0; m[mt][1] = nm1;
                    #pragma unroll
                    for (int nd = 0; nd < 4; nd++) {
                        o[mt][nd][0] *= c0; o[mt][nd][1] *= c0;
                        o[mt][nd][2] *= c1; o[mt][nd][3] *= c1;
                    }
                    lacc[mt][0] *= c0; lacc[mt][2] *= c1;
                }
                float mK0 = -m[mt][0] * KDEC, mK1 = -m[mt][1] * KDEC;
                #pragma unroll
                for (int kk = 0; kk < 2; kk++) {
                    pa[mt][kk][0] = ex2_h2(fmaf(sc[mt][2*kk][0],   KDEC, mK0),
                                           fmaf(sc[mt][2*kk][1],   KDEC, mK0));
                    pa[mt][kk][1] = ex2_h2(fmaf(sc[mt][2*kk][2],   KDEC, mK1),
                                           fmaf(sc[mt][2*kk][3],   KDEC, mK1));
                    pa[mt][kk][2] = ex2_h2(fmaf(sc[mt][2*kk+1][0], KDEC, mK0),
                                           fmaf(sc[mt][2*kk+1][1], KDEC, mK0));
                    pa[mt][kk][3] = ex2_h2(fmaf(sc[mt][2*kk+1][2], KDEC, mK1),
                                           fmaf(sc[mt][2*kk+1][3], KDEC, mK1));
                }
                #pragma unroll
                for (int kk = 0; kk < 2; kk++)
                    mma_f16(lacc[mt], pa[mt][kk], ONES_H2, ONES_H2);
            }

            // ---- O += P V ----
            #pragma unroll
            for (int ndp = 0; ndp < 2; ndp++)
                #pragma unroll
                for (int kk = 0; kk < 2; kk++) {
                    uint32_t vb[4];
                    int key = sh * 32 + kk * 16 + (lane & 15);
                    int kch = ndp * 2 + (lane >> 4);
                    ldsm4t(vb, vS[s] + swz(key, kch));
                    #pragma unroll
                    for (int mt = 0; mt < 2; mt++) {
                        mma_f16(o[mt][ndp * 2],     pa[mt][kk], vb[0], vb[1]);
                        mma_f16(o[mt][ndp * 2 + 1], pa[mt][kk], vb[2], vb[3]);
                    }
                }
        }
        s = (s == 2) ? 0 : s + 1;
    }

    // finalize
    #pragma unroll
    for (int mt = 0; mt < 2; mt++) {
        float i0 = 1.f / lacc[mt][0], i1 = 1.f / lacc[mt][2];
        __half* op0 = g_att + ((size_t)b * NTOK + q0 + mt * 16 + g) * DIM + h * HD;
        __half* op8 = op0 + (size_t)8 * DIM;
        #pragma unroll
        for (int nd = 0; nd < 4; nd++) {
            *(uint32_t*)(op0 + nd * 8 + 2 * t)
                = pack_half2(o[mt][nd][0] * i0, o[mt][nd][1] * i0);
            *(uint32_t*)(op8 + nd * 8 + 2 * t)
                = pack_half2(o[mt][nd][2] * i1, o[mt][nd][3] * i1);
        }
    }
}

// ---------------- launch ----------------
extern "C" void kernel_launch(void* const* d_in, const int* in_sizes, int n_in,
                              void* d_out, int out_size) {
    const float* x      = (const float*)d_in[0];
    const float* mask   = (const float*)d_in[1];
    const float* qkv_w  = (const float*)d_in[2];
    const float* proj_w = (const float*)d_in[3];
    const float* proj_b = (const float*)d_in[4];
    const float* cpb_w1 = (const float*)d_in[5];
    const float* cpb_b1 = (const float*)d_in[6];
    const float* cpb_w2 = (const float*)d_in[7];
    const float* rpb    = (const float*)d_in[8];
    const int*   rpb_idx = (const int*)d_in[9];
    float* out = (float*)d_out;

    static __half *p_xh = nullptr, *p_qkvw = nullptr, *p_projw = nullptr,
                  *p_qkv = nullptr, *p_att = nullptr;
    if (!p_xh) {
        cudaGetSymbolAddress((void**)&p_xh, g_xh);
        cudaGetSymbolAddress((void**)&p_qkvw, g_qkvw);
        cudaGetSymbolAddress((void**)&p_projw, g_projw);
        cudaGetSymbolAddress((void**)&p_qkv, g_qkv);
        cudaGetSymbolAddress((void**)&p_att, g_att);
        cudaFuncSetAttribute(gemm_h,
                             cudaFuncAttributeMaxDynamicSharedMemorySize, GSMEM);
    }

    prep0<<<NCVT_BLK + TABLE_E, 256>>>(x, qkv_w, proj_w,
                                       rpb, cpb_w1, cpb_b1, cpb_w2);
    prep1<<<4096 + 32768 / 256, 256>>>(mask, rpb_idx);
    {
        dim3 grid(QKV_LD / 128, (BATCH * NTOK) / 128);
        gemm_h<<<grid, 128, GSMEM>>>(p_xh, p_qkvw, nullptr, p_qkv,
                                     BATCH * NTOK, QKV_LD, DIM, 0,
                                     DIM, SCALE2 * RAWK);
    }
    attn_h<<<dim3(NTOK / 128, NH, BATCH), 128>>>();
    {
        dim3 grid(DIM / 128, (BATCH * NTOK) / 128);
        gemm_h<<<grid, 128, GSMEM>>>(p_att, p_projw, proj_b, out,
                                     BATCH * NTOK, DIM, DIM, 1, 0, 1.f);
    }
}

// round 15
// speedup vs baseline: 1.0366x; 1.0366x over previous
#include <cuda_runtime.h>
#include <cuda_fp16.h>
#include <math.h>
#include <stdint.h>

#define BATCH   128
#define NWIN    16
#define NTOK    512
#define DIM     256
#define NH      8
#define HD      32
#define TABLE_E 3375
#define QKV_LD  768
#define NN      (NTOK*NTOK)
#define LOG2E   1.4426950408889634f
#define NFRAG   65536
#define ONES_H2 0x3C003C00u
#define SCALE2  (0.17677669529663687f * LOG2E)
#define RAWK    (65536.f / 24.f)         // raw units per log2-unit
#define KDEC    (24.f / 65536.f)         // log2-units per raw unit

// ---------------- scratch (device globals) ----------------
__device__ float  g_table[TABLE_E * NH];
__device__ uint4  g_biasU[NH * 32768];      // u16 fixed-point bias (raw units), 4 MB
__device__ float4 g_maskF[NWIN * NFRAG];    // fragment-layout mask (raw units)
__device__ int    g_maskflag;
__device__ __half g_xh[(size_t)BATCH * NTOK * DIM];
__device__ __half g_qkvw[QKV_LD * DIM];
__device__ __half g_projw[DIM * DIM];
__device__ __half g_qkv[(size_t)BATCH * NTOK * QKV_LD];   // Q pre-scaled to raw units
__device__ __half g_att[(size_t)BATCH * NTOK * DIM];

// =====================  helpers  =====================
__device__ __forceinline__ uint32_t pack_half2(float lo, float hi) {
    __half2 h = __floats2half2_rn(lo, hi);
    return *(uint32_t*)&h;
}
__device__ __forceinline__ uint32_t ex2_h2(float lo, float hi) {
    uint32_t d = pack_half2(lo, hi), r;
    asm("ex2.approx.f16x2 %0, %1;" : "=r"(r) : "r"(d));
    return r;
}
__device__ __forceinline__ void mma_f16(float* d, const uint32_t* a,
                                        uint32_t b0, uint32_t b1) {
    asm volatile(
        "mma.sync.aligned.m16n8k16.row.col.f32.f16.f16.f32 "
        "{%0,%1,%2,%3}, {%4,%5,%6,%7}, {%8,%9}, {%0,%1,%2,%3};"
        : "+f"(d[0]), "+f"(d[1]), "+f"(d[2]), "+f"(d[3])
        : "r"(a[0]), "r"(a[1]), "r"(a[2]), "r"(a[3]), "r"(b0), "r"(b1));
}
__device__ __forceinline__ void ldsm4(uint32_t* r, uint32_t addr) {
    asm volatile("ldmatrix.sync.aligned.m8n8.x4.shared.b16 {%0,%1,%2,%3}, [%4];"
                 : "=r"(r[0]), "=r"(r[1]), "=r"(r[2]), "=r"(r[3]) : "r"(addr));
}
__device__ __forceinline__ void ldsm4t(uint32_t* r, uint32_t addr) {
    asm volatile("ldmatrix.sync.aligned.m8n8.x4.trans.shared.b16 {%0,%1,%2,%3}, [%4];"
                 : "=r"(r[0]), "=r"(r[1]), "=r"(r[2]), "=r"(r[3]) : "r"(addr));
}
__device__ __forceinline__ uint32_t cvta_s(const void* p) {
    return (uint32_t)__cvta_generic_to_shared(p);
}
__device__ __forceinline__ uint32_t swz(int r, int kchunk) {
    return (uint32_t)(r * 64 + ((kchunk ^ ((r >> 1) & 3)) << 4));
}
__device__ __forceinline__ uint32_t swz128(int r, int kchunk) {
    return (uint32_t)(r * 128 + ((kchunk ^ (r & 7)) << 4));
}
__device__ __forceinline__ void cp16(uint32_t smem, const void* g) {
    asm volatile("cp.async.cg.shared.global [%0], [%1], 16;"
                 :: "r"(smem), "l"(g) : "memory");
}
__device__ __forceinline__ void cp_commit() {
    asm volatile("cp.async.commit_group;" ::: "memory");
}
__device__ __forceinline__ void cp_wait0() {
    asm volatile("cp.async.wait_group 0;" ::: "memory");
}

// ---------------- prep0: fp32->fp16 conversions + CPB MLP ----------------
#define N8X ((BATCH * NTOK * DIM) / 8)
#define N8W ((QKV_LD * DIM) / 8)
#define N8P ((DIM * DIM) / 8)
#define N8T (N8X + N8W + N8P)
#define NCVT_BLK ((N8T + 255) / 256)
__global__ void prep0(const float* __restrict__ x,
                      const float* __restrict__ qw,
                      const float* __restrict__ pw,
                      const float* __restrict__ rpb,
                      const float* __restrict__ w1,
                      const float* __restrict__ b1,
                      const float* __restrict__ w2) {
    int bx = blockIdx.x;
    if (bx < NCVT_BLK) {
        int i = bx * 256 + threadIdx.x;
        if (i == 0) g_maskflag = 0;
        const float* s;
        __half* d;
        int j;
        if (i < N8X)                  { s = x;  d = g_xh;    j = i; }
        else if (i < N8X + N8W)       { s = qw; d = g_qkvw;  j = i - N8X; }
        else if (i < N8T)             { s = pw; d = g_projw; j = i - N8X - N8W; }
        else return;
        const float4* sp = (const float4*)s + (size_t)j * 2;
        float4 a = sp[0], b = sp[1];
        uint4 o;
        o.x = pack_half2(a.x, a.y); o.y = pack_half2(a.z, a.w);
        o.z = pack_half2(b.x, b.y); o.w = pack_half2(b.z, b.w);
        ((uint4*)d)[j] = o;
    } else {
        int e = bx - NCVT_BLK;
        int h = threadIdx.x >> 5;
        int lane = threadIdx.x & 31;
        float r0 = rpb[e * 3 + 0], r1 = rpb[e * 3 + 1], r2 = rpb[e * 3 + 2];
        float sum = 0.f;
        for (int o = lane; o < 512; o += 32) {
            float hid = fmaf(r0, w1[o * 3 + 0],
                        fmaf(r1, w1[o * 3 + 1],
                        fmaf(r2, w1[o * 3 + 2], b1[o])));
            hid = fmaxf(hid, 0.f);
            sum = fmaf(hid, w2[h * 512 + o], sum);
        }
        #pragma unroll
        for (int off = 16; off; off >>= 1)
            sum += __shfl_xor_sync(0xffffffffu, sum, off);
        if (lane == 0) g_table[e * NH + h] = sum;
    }
}

// ---------------- prep1: maskF (raw units) + biasU (u16) -------------------
__global__ void prep1(const float* __restrict__ mask,
                      const int* __restrict__ rpb_idx) {
    int bx = blockIdx.x;
    if (bx < 4096) {
        int w = bx >> 8;
        int i = (bx & 255) * 256 + threadIdx.x;
        int g = i & 7, t = (i >> 3) & 3, jn = (i >> 5) & 7, c = (i >> 8) & 7;
        int wid = (i >> 11) & 7, qt = i >> 14;
        int q0 = qt * 128 + wid * 16 + g;
        int k0 = c * 64 + jn * 8 + 2 * t;
        const float* mw = mask + (size_t)w * NN;
        float4 v;
        v.x = mw[q0 * NTOK + k0];
        v.y = mw[q0 * NTOK + k0 + 1];
        v.z = mw[(q0 + 8) * NTOK + k0];
        v.w = mw[(q0 + 8) * NTOK + k0 + 1];
        bool nz = (v.x != 0.f) | (v.y != 0.f) | (v.z != 0.f) | (v.w != 0.f);
        const float MS = LOG2E * RAWK;
        v.x *= MS; v.y *= MS; v.z *= MS; v.w *= MS;
        g_maskF[(size_t)w * NFRAG + i] = v;
        if (__syncthreads_or(nz) && threadIdx.x == 0)
            atomicOr(&g_maskflag, 1);
    } else {
        int i = (bx - 4096) * 256 + threadIdx.x;
        int g = i & 7, t = (i >> 3) & 3, jp = (i >> 5) & 1, sh = (i >> 6) & 1;
        int c = (i >> 7) & 7, we = (i >> 10) & 7, qt = i >> 13;
        int q0 = qt * 128 + we * 16 + g;
        int kbase = c * 64 + sh * 32 + jp * 16 + 2 * t;
        int idx[8];
        #pragma unroll
        for (int jj = 0; jj < 2; jj++) {
            int k0 = kbase + jj * 8;
            idx[jj * 4 + 0] = rpb_idx[q0 * NTOK + k0];
            idx[jj * 4 + 1] = rpb_idx[q0 * NTOK + k0 + 1];
            idx[jj * 4 + 2] = rpb_idx[(q0 + 8) * NTOK + k0];
            idx[jj * 4 + 3] = rpb_idx[(q0 + 8) * NTOK + k0 + 1];
        }
        const float KENC = 16.f * LOG2E * RAWK;
        size_t obase = (size_t)qt * 8192 + we * 1024 + c * 128 + sh * 64
                     + jp * 32 + t * 8 + g;
        #pragma unroll
        for (int h = 0; h < NH; h++) {
            uint32_t u[8];
            #pragma unroll
            for (int v = 0; v < 8; v++) {
                float val = KENC / (1.f + __expf(-g_table[idx[v] * NH + h]));
                u[v] = (uint32_t)(val + 0.5f);
            }
            uint4 o4;
            o4.x = u[0] | (u[1] << 16);
            o4.y = u[2] | (u[3] << 16);
            o4.z = u[4] | (u[5] << 16);
            o4.w = u[6] | (u[7] << 16);
            g_biasU[(size_t)h * 32768 + obase] = o4;
        }
    }
}

// =====================  fp16 mma GEMM (NT), 64x64 warp tiles, BK=64  =====
#define GSMEM (4 * 16384)
__global__ __launch_bounds__(128, 2) void gemm_h(const __half* __restrict__ A,
                                                 const __half* __restrict__ B,
                                                 const float* __restrict__ bias,
                                                 void* __restrict__ Cv,
                                                 int M, int N, int K, int fp32out,
                                                 int qcols, float qsc) {
    extern __shared__ __align__(16) char gsm[];
    const int tid = threadIdx.x, lane = tid & 31, wid = tid >> 5;
    const int g = lane >> 2, t = lane & 3;
    const int wm = wid & 1, wn = wid >> 1;
    const int row0 = blockIdx.y * 128, col0 = blockIdx.x * 128;

    const int lr0 = tid >> 3, lc = tid & 7;
    const __half* Ap = A + (size_t)(row0 + lr0) * K + lc * 8;
    const __half* Bp = B + (size_t)(col0 + lr0) * K + lc * 8;
    const size_t rstep = (size_t)16 * K;
    uint32_t aS[2] = { cvta_s(gsm), cvta_s(gsm) + 16384 };
    uint32_t bS[2] = { cvta_s(gsm) + 32768, cvta_s(gsm) + 49152 };
    uint32_t soffs[8];
    #pragma unroll
    for (int i = 0; i < 8; i++) soffs[i] = swz128(lr0 + i * 16, lc);

    float acc[4][8][4];
    #pragma unroll
    for (int mt = 0; mt < 4; mt++)
        #pragma unroll
        for (int jn = 0; jn < 8; jn++)
            #pragma unroll
            for (int r = 0; r < 4; r++) acc[mt][jn][r] = 0.f;

    #pragma unroll
    for (int i = 0; i < 8; i++) {
        cp16(aS[0] + soffs[i], Ap + i * rstep);
        cp16(bS[0] + soffs[i], Bp + i * rstep);
    }
    cp_commit();

    const int nk = K >> 6;
    for (int kt = 0; kt < nk; kt++) {
        const int s = kt & 1;
        cp_wait0();
        __syncthreads();
        if (kt + 1 < nk) {
            int ko = (kt + 1) * 64;
            #pragma unroll
            for (int i = 0; i < 8; i++) {
                cp16(aS[s ^ 1] + soffs[i], Ap + i * rstep + ko);
                cp16(bS[s ^ 1] + soffs[i], Bp + i * rstep + ko);
            }
            cp_commit();
        }
        #pragma unroll
        for (int ks = 0; ks < 4; ks++) {
            uint32_t af[4][4];
            #pragma unroll
            for (int mt = 0; mt < 4; mt++) {
                int row = wm * 64 + mt * 16 + (lane & 15);
                int kch = ks * 2 + (lane >> 4);
                ldsm4(af[mt], aS[s] + swz128(row, kch));
            }
            uint32_t bf[4][4];
            #pragma unroll
            for (int i = 0; i < 4; i++) {
                int rn = wn * 64 + i * 16 + ((lane >> 4) << 3) + (lane & 7);
                int kch = ks * 2 + ((lane & 8) >> 3);
                ldsm4(bf[i], bS[s] + swz128(rn, kch));
            }
            #pragma unroll
            for (int mt = 0; mt < 4; mt++)
                #pragma unroll
                for (int jn = 0; jn < 8; jn++)
                    mma_f16(acc[mt][jn], af[mt],
                            bf[jn >> 1][(jn & 1) * 2], bf[jn >> 1][(jn & 1) * 2 + 1]);
        }
        // no trailing sync: next iteration's wait0+sync orders buffer reuse
    }

    if (fp32out) {
        float* C = (float*)Cv;
        #pragma unroll
        for (int mt = 0; mt < 4; mt++) {
            int r = row0 + wm * 64 + mt * 16;
            #pragma unroll
            for (int jn = 0; jn < 8; jn++) {
                int cc = col0 + wn * 64 + jn * 8 + 2 * t;
                float bx = bias[cc], by = bias[cc + 1];
                float2 v0 = { acc[mt][jn][0] + bx, acc[mt][jn][1] + by };
                float2 v1 = { acc[mt][jn][2] + bx, acc[mt][jn][3] + by };
                *(float2*)(C + (size_t)(r + g) * N + cc) = v0;
                *(float2*)(C + (size_t)(r + g + 8) * N + cc) = v1;
            }
        }
    } else {
        __half* C = (__half*)Cv;
        #pragma unroll
        for (int mt = 0; mt < 4; mt++) {
            int r = row0 + wm * 64 + mt * 16;
            #pragma unroll
            for (int jn = 0; jn < 8; jn++) {
                int cc = col0 + wn * 64 + jn * 8 + 2 * t;
                float sc_ = (cc < qcols) ? qsc : 1.f;
                *(uint32_t*)(C + (size_t)(r + g) * N + cc)
                    = pack_half2(acc[mt][jn][0] * sc_, acc[mt][jn][1] * sc_);
                *(uint32_t*)(C + (size_t)(r + g + 8) * N + cc)
                    = pack_half2(acc[mt][jn][2] * sc_, acc[mt][jn][3] * sc_);
            }
        }
    }
}

// =====================  fused fp16 mma attention ============================
// R13 structure (2-buffer, unconditional rescale) with trailing sync removed
__global__ __launch_bounds__(128, 3) void attn_h() {
    __shared__ __align__(16) __half Ks[2][64 * 32];
    __shared__ __align__(16) __half Vs[2][64 * 32];
    const int qt = blockIdx.x, h = blockIdx.y, b = blockIdx.z;
    const int tid = threadIdx.x, lane = tid & 31, w = tid >> 5;
    const int g = lane >> 2, t = lane & 3;
    const int q0 = qt * 128 + w * 32;
    const __half* base = g_qkv + (size_t)b * NTOK * QKV_LD;
    const bool use_mask = (g_maskflag != 0);

    const __half* kp0 = base + (size_t)(tid >> 2) * QKV_LD + DIM + h * HD + (tid & 3) * 8;
    const __half* kp1 = base + (size_t)((tid + 128) >> 2) * QKV_LD + DIM + h * HD
                             + ((tid + 128) & 3) * 8;
    const uint32_t sf0 = swz(tid >> 2, tid & 3);
    const uint32_t sf1 = swz((tid + 128) >> 2, (tid + 128) & 3);
    const uint32_t kS[2] = { cvta_s(Ks[0]), cvta_s(Ks[1]) };
    const uint32_t vS[2] = { cvta_s(Vs[0]), cvta_s(Vs[1]) };

    cp16(kS[0] + sf0, kp0);
    cp16(kS[0] + sf1, kp1);
    cp16(vS[0] + sf0, kp0 + DIM);
    cp16(vS[0] + sf1, kp1 + DIM);
    cp_commit();

    uint32_t qa[2][2][4];   // Q already in raw units
    #pragma unroll
    for (int mt = 0; mt < 2; mt++) {
        const __half* qp0 = base + (size_t)(q0 + mt * 16 + g) * QKV_LD + h * HD;
        const __half* qp8 = qp0 + (size_t)8 * QKV_LD;
        #pragma unroll
        for (int ks = 0; ks < 2; ks++) {
            qa[mt][ks][0] = *(const uint32_t*)(qp0 + ks * 16 + 2 * t);
            qa[mt][ks][1] = *(const uint32_t*)(qp8 + ks * 16 + 2 * t);
            qa[mt][ks][2] = *(const uint32_t*)(qp0 + ks * 16 + 8 + 2 * t);
            qa[mt][ks][3] = *(const uint32_t*)(qp8 + ks * 16 + 8 + 2 * t);
        }
    }

    float o[2][4][4];
    float lacc[2][4];
    #pragma unroll
    for (int mt = 0; mt < 2; mt++) {
        #pragma unroll
        for (int nd = 0; nd < 4; nd++)
            #pragma unroll
            for (int r = 0; r < 4; r++) o[mt][nd][r] = 0.f;
        #pragma unroll
        for (int r = 0; r < 4; r++) lacc[mt][r] = 0.f;
    }
    float m[2][2] = { { -1e30f, -1e30f }, { -1e30f, -1e30f } };

    const uint4* bU[2];
    const float4* mp4[2];
    #pragma unroll
    for (int mt = 0; mt < 2; mt++) {
        int we = w * 2 + mt;
        bU[mt] = g_biasU + (size_t)h * 32768 + (size_t)qt * 8192 + we * 1024
               + t * 8 + g;
        mp4[mt] = g_maskF + (((size_t)(b & (NWIN - 1)) * 4 + qt) * 8 + we) * 2048
                + t * 8 + g;
    }

    for (int c = 0; c < 8; c++) {
        const int s = c & 1;
        cp_wait0();
        __syncthreads();
        if (c < 7) {
            const size_t nb = (size_t)(c + 1) * 64 * QKV_LD;
            cp16(kS[s ^ 1] + sf0, kp0 + nb);
            cp16(kS[s ^ 1] + sf1, kp1 + nb);
            cp16(vS[s ^ 1] + sf0, kp0 + nb + DIM);
            cp16(vS[s ^ 1] + sf1, kp1 + nb + DIM);
            cp_commit();
        }

        // two 32-key sub-chunks
        #pragma unroll
        for (int sh = 0; sh < 2; sh++) {
            // ---- S init = bias (u16 decode, raw units) (+ mask) ----
            float sc[2][4][4];
            #pragma unroll
            for (int mt = 0; mt < 2; mt++) {
                const uint4* bu = bU[mt] + c * 128 + sh * 64;
                uint4 U0 = bu[0];
                uint4 U1 = bu[32];
                sc[mt][0][0] = (float)(U0.x & 0xffffu); sc[mt][0][1] = (float)(U0.x >> 16);
                sc[mt][0][2] = (float)(U0.y & 0xffffu); sc[mt][0][3] = (float)(U0.y >> 16);
                sc[mt][1][0] = (float)(U0.z & 0xffffu); sc[mt][1][1] = (float)(U0.z >> 16);
                sc[mt][1][2] = (float)(U0.w & 0xffffu); sc[mt][1][3] = (float)(U0.w >> 16);
                sc[mt][2][0] = (float)(U1.x & 0xffffu); sc[mt][2][1] = (float)(U1.x >> 16);
                sc[mt][2][2] = (float)(U1.y & 0xffffu); sc[mt][2][3] = (float)(U1.y >> 16);
                sc[mt][3][0] = (float)(U1.z & 0xffffu); sc[mt][3][1] = (float)(U1.z >> 16);
                sc[mt][3][2] = (float)(U1.w & 0xffffu); sc[mt][3][3] = (float)(U1.w >> 16);
                if (use_mask) {
                    const float4* mc = mp4[mt] + c * 256 + sh * 128;
                    #pragma unroll
                    for (int jn = 0; jn < 4; jn++) {
                        float4 mv = mc[jn * 32];
                        sc[mt][jn][0] += mv.x; sc[mt][jn][1] += mv.y;
                        sc[mt][jn][2] += mv.z; sc[mt][jn][3] += mv.w;
                    }
                }
            }
            // ---- S += Q K^T (raw units) ----
            #pragma unroll
            for (int ks = 0; ks < 2; ks++) {
                uint32_t kb[2][4];
                #pragma unroll
                for (int i = 0; i < 2; i++) {
                    int rn = sh * 32 + i * 16 + ((lane >> 4) << 3) + (lane & 7);
                    int kch = ks * 2 + ((lane & 8) >> 3);
                    ldsm4(kb[i], kS[s] + swz(rn, kch));
                }
                #pragma unroll
                for (int jn = 0; jn < 4; jn++) {
                    uint32_t b0 = kb[jn >> 1][(jn & 1) * 2];
                    uint32_t b1 = kb[jn >> 1][(jn & 1) * 2 + 1];
                    mma_f16(sc[0][jn], qa[0][ks], b0, b1);
                    mma_f16(sc[1][jn], qa[1][ks], b0, b1);
                }
            }

            // ---- online softmax (raw units, unconditional rescale) ----
            uint32_t pa[2][2][4];
            #pragma unroll
            for (int mt = 0; mt < 2; mt++) {
                float mx0 = sc[mt][0][0], mx1 = sc[mt][0][2];
                #pragma unroll
                for (int jn = 0; jn < 4; jn++) {
                    mx0 = fmaxf(mx0, fmaxf(sc[mt][jn][0], sc[mt][jn][1]));
                    mx1 = fmaxf(mx1, fmaxf(sc[mt][jn][2], sc[mt][jn][3]));
                }
                mx0 = fmaxf(mx0, __shfl_xor_sync(0xffffffffu, mx0, 1));
                mx0 = fmaxf(mx0, __shfl_xor_sync(0xffffffffu, mx0, 2));
                mx1 = fmaxf(mx1, __shfl_xor_sync(0xffffffffu, mx1, 1));
                mx1 = fmaxf(mx1, __shfl_xor_sync(0xffffffffu, mx1, 2));
                float nm0 = fmaxf(m[mt][0], mx0), nm1 = fmaxf(m[mt][1], mx1);
                float c0 = exp2f((m[mt][0] - nm0) * KDEC);
                float c1 = exp2f((m[mt][1] - nm1) * KDEC);
                m[mt][0] = nm0; m[mt][1] = nm1;
                #pragma unroll
                for (int nd = 0; nd < 4; nd++) {
                    o[mt][nd][0] *= c0; o[mt][nd][1] *= c0;
                    o[mt][nd][2] *= c1; o[mt][nd][3] *= c1;
                }
                lacc[mt][0] *= c0; lacc[mt][2] *= c1;
                float mK0 = -nm0 * KDEC, mK1 = -nm1 * KDEC;
                #pragma unroll
                for (int kk = 0; kk < 2; kk++) {
                    pa[mt][kk][0] = ex2_h2(fmaf(sc[mt][2*kk][0],   KDEC, mK0),
                                           fmaf(sc[mt][2*kk][1],   KDEC, mK0));
                    pa[mt][kk][1] = ex2_h2(fmaf(sc[mt][2*kk][2],   KDEC, mK1),
                                           fmaf(sc[mt][2*kk][3],   KDEC, mK1));
                    pa[mt][kk][2] = ex2_h2(fmaf(sc[mt][2*kk+1][0], KDEC, mK0),
                                           fmaf(sc[mt][2*kk+1][1], KDEC, mK0));
                    pa[mt][kk][3] = ex2_h2(fmaf(sc[mt][2*kk+1][2], KDEC, mK1),
                                           fmaf(sc[mt][2*kk+1][3], KDEC, mK1));
                }
                #pragma unroll
                for (int kk = 0; kk < 2; kk++)
                    mma_f16(lacc[mt], pa[mt][kk], ONES_H2, ONES_H2);
            }

            // ---- O += P V ----
            #pragma unroll
            for (int ndp = 0; ndp < 2; ndp++)
                #pragma unroll
                for (int kk = 0; kk < 2; kk++) {
                    uint32_t vb[4];
                    int key = sh * 32 + kk * 16 + (lane & 15);
                    int kch = ndp * 2 + (lane >> 4);
                    ldsm4t(vb, vS[s] + swz(key, kch));
                    #pragma unroll
                    for (int mt = 0; mt < 2; mt++) {
                        mma_f16(o[mt][ndp * 2],     pa[mt][kk], vb[0], vb[1]);
                        mma_f16(o[mt][ndp * 2 + 1], pa[mt][kk], vb[2], vb[3]);
                    }
                }
        }
        // no trailing sync: next iteration's wait0+sync orders buffer reuse
    }

    // finalize
    #pragma unroll
    for (int mt = 0; mt < 2; mt++) {
        float i0 = 1.f / lacc[mt][0], i1 = 1.f / lacc[mt][2];
        __half* op0 = g_att + ((size_t)b * NTOK + q0 + mt * 16 + g) * DIM + h * HD;
        __half* op8 = op0 + (size_t)8 * DIM;
        #pragma unroll
        for (int nd = 0; nd < 4; nd++) {
            *(uint32_t*)(op0 + nd * 8 + 2 * t)
                = pack_half2(o[mt][nd][0] * i0, o[mt][nd][1] * i0);
            *(uint32_t*)(op8 + nd * 8 + 2 * t)
                = pack_half2(o[mt][nd][2] * i1, o[mt][nd][3] * i1);
        }
    }
}

// ---------------- launch ----------------
extern "C" void kernel_launch(void* const* d_in, const int* in_sizes, int n_in,
                              void* d_out, int out_size) {
    const float* x      = (const float*)d_in[0];
    const float* mask   = (const float*)d_in[1];
    const float* qkv_w  = (const float*)d_in[2];
    const float* proj_w = (const float*)d_in[3];
    const float* proj_b = (const float*)d_in[4];
    const float* cpb_w1 = (const float*)d_in[5];
    const float* cpb_b1 = (const float*)d_in[6];
    const float* cpb_w2 = (const float*)d_in[7];
    const float* rpb    = (const float*)d_in[8];
    const int*   rpb_idx = (const int*)d_in[9];
    float* out = (float*)d_out;

    static __half *p_xh = nullptr, *p_qkvw = nullptr, *p_projw = nullptr,
                  *p_qkv = nullptr, *p_att = nullptr;
    if (!p_xh) {
        cudaGetSymbolAddress((void**)&p_xh, g_xh);
        cudaGetSymbolAddress((void**)&p_qkvw, g_qkvw);
        cudaGetSymbolAddress((void**)&p_projw, g_projw);
        cudaGetSymbolAddress((void**)&p_qkv, g_qkv);
        cudaGetSymbolAddress((void**)&p_att, g_att);
        cudaFuncSetAttribute(gemm_h,
                             cudaFuncAttributeMaxDynamicSharedMemorySize, GSMEM);
    }

    prep0<<<NCVT_BLK + TABLE_E, 256>>>(x, qkv_w, proj_w,
                                       rpb, cpb_w1, cpb_b1, cpb_w2);
    prep1<<<4096 + 32768 / 256, 256>>>(mask, rpb_idx);
    {
        dim3 grid(QKV_LD / 128, (BATCH * NTOK) / 128);
        gemm_h<<<grid, 128, GSMEM>>>(p_xh, p_qkvw, nullptr, p_qkv,
                                     BATCH * NTOK, QKV_LD, DIM, 0,
                                     DIM, SCALE2 * RAWK);
    }
    attn_h<<<dim3(NTOK / 128, NH, BATCH), 128>>>();
    {
        dim3 grid(DIM / 128, (BATCH * NTOK) / 128);
        gemm_h<<<grid, 128, GSMEM>>>(p_att, p_projw, proj_b, out,
                                     BATCH * NTOK, DIM, DIM, 1, 0, 1.f);
    }
}